// round 11
// baseline (speedup 1.0000x reference)
#include <cuda_runtime.h>
#include <cstdint>

// Forward 5/3 lifting wavelet, 2D separable, fused tile kernel.
// Persistent-CTA version with L2 prefetch of each CTA's next tile.
// x: (8, 32, 512, 512) f32 -> out: (8, 128, 256, 256) f32
// out channels: [LL(0:32) | LH(32:64) | HL(64:96) | HH(96:128)]
//
//   d[i] = odd[i] - 0.5*(even[il] + even[ir]), il=(i==0)?1:i-1, ir=(i==255)?254:i+1
//   s[i] = even[i] + 0.25*(d[il] + d[ir])     (same reflected indices)
//
// R=8 rows/strip, 256-thread CTAs, 47KB smem -> 4 CTAs/SM. Each CTA loops
// over strips with stride gridDim; at the top of each iteration it issues
// prefetch.global.L2 for its NEXT tile so Phase-A demand loads hit L2.

static constexpr int H = 512;
static constexpr int Wd = 512;
static constexpr int R = 8;               // output rows per strip
static constexpr int NSTRIP = 256 / R;    // 32
static constexpr int NBC = 8 * 32;        // 256 images
static constexpr int NTILES = NBC * NSTRIP; // 8192
static constexpr int MAXROWS = 2 * R + 7; // 23
static constexpr int SMEM_BYTES = MAXROWS * Wd * 4; // 47104
static constexpr int GRID = 608;          // ~4 CTAs/SM on 148-152 SMs

static constexpr unsigned FULL = 0xffffffffu;

__device__ __forceinline__ float2 f2_add(float2 a, float2 b) {
    return make_float2(a.x + b.x, a.y + b.y);
}
__device__ __forceinline__ float2 f2_fma(float k, float2 a, float2 b) {
    return make_float2(fmaf(k, a.x, b.x), fmaf(k, a.y, b.y));
}

__global__ __launch_bounds__(256, 4)
void lwt53_fused_kernel(const float* __restrict__ x, float* __restrict__ out) {
    extern __shared__ float A[];   // [23 slots][512]; per row: s in [0,256), d in [256,512)

    const int tid  = threadIdx.x;
    const int warp = tid >> 5;
    const int lane = tid & 31;

    for (int w = blockIdx.x; w < NTILES; w += GRID) {
        const int strip = w & (NSTRIP - 1);
        const int bc    = w >> 5;
        const int r0    = strip * R;

        const int mlo   = max(0, 2 * r0 - 4);
        const int mhi   = min(H - 1, 2 * r0 + 2 * R + 2);
        const int nrows = mhi - mlo + 1;

        const float* __restrict__ xim = x + (size_t)bc * (H * Wd) + (size_t)mlo * Wd;

        // ---- L2 prefetch of the NEXT tile (fire-and-forget) ----
        {
            const int wn = w + GRID;
            if (wn < NTILES) {
                const int strip_n = wn & (NSTRIP - 1);
                const int bc_n    = wn >> 5;
                const int r0_n    = strip_n * R;
                const int mlo_n   = max(0, 2 * r0_n - 4);
                const int mhi_n   = min(H - 1, 2 * r0_n + 2 * R + 2);
                const int nl      = (mhi_n - mlo_n + 1) * 16;   // 128B lines
                const float* __restrict__ xn =
                    x + (size_t)bc_n * (H * Wd) + (size_t)mlo_n * Wd;
                for (int i = tid; i < nl; i += 256) {
                    const float* p = xn + (size_t)(i >> 4) * Wd + (i & 15) * 32;
                    asm volatile("prefetch.global.L2 [%0];" :: "l"(p));
                }
            }
        }

        // ================= Phase A: row lifting in registers =================
        for (int r = warp; r < nrows; r += 8) {
            if (r == 1 && r0 > 0) continue;    // dead halo row for interior strips
            const float4* __restrict__ xr =
                reinterpret_cast<const float4*>(xim + (size_t)r * Wd);
            float eA[4], oA[4], eB[4], oB[4];
            #pragma unroll
            for (int j = 0; j < 4; j++) {
                const float4 v = xr[32 * j + lane];
                eA[j] = v.x; oA[j] = v.y; eB[j] = v.z; oB[j] = v.w;
            }

            float dA[4], dB[4];
            #pragma unroll
            for (int j = 0; j < 4; j++) {
                float up = __shfl_up_sync(FULL, eB[j], 1);
                float cp = __shfl_sync(FULL, (j > 0) ? eB[j - 1] : eB[j], 31);
                float Eprev = (lane == 0) ? ((j == 0) ? eB[0] : cp) : up;   // refl i=0
                float dn = __shfl_down_sync(FULL, eA[j], 1);
                float cn = __shfl_sync(FULL, (j < 3) ? eA[j + 1] : eA[j], 0);
                float Enext = (lane == 31) ? ((j == 3) ? eA[3] : cn) : dn;  // refl i=255
                dA[j] = oA[j] - 0.5f * (Eprev + eB[j]);
                dB[j] = oB[j] - 0.5f * (eA[j] + Enext);
            }

            float* Arow = A + r * Wd;
            float2* __restrict__ srow = reinterpret_cast<float2*>(Arow);
            float2* __restrict__ drow = reinterpret_cast<float2*>(Arow + 256);
            #pragma unroll
            for (int j = 0; j < 4; j++) {
                float up = __shfl_up_sync(FULL, dB[j], 1);
                float cp = __shfl_sync(FULL, (j > 0) ? dB[j - 1] : dB[j], 31);
                float Dprev = (lane == 0) ? ((j == 0) ? dB[0] : cp) : up;
                float dn = __shfl_down_sync(FULL, dA[j], 1);
                float cn = __shfl_sync(FULL, (j < 3) ? dA[j + 1] : dA[j], 0);
                float Dnext = (lane == 31) ? ((j == 3) ? dA[3] : cn) : dn;
                float sA = eA[j] + 0.25f * (Dprev + dB[j]);
                float sB = eB[j] + 0.25f * (dA[j] + Dnext);
                srow[32 * j + lane] = make_float2(sA, sB);
                drow[32 * j + lane] = make_float2(dA[j], dB[j]);
            }
        }
        __syncthreads();

        // ============ Phase B: column lifting, 3-term sliding window ============
        {
            const int t  = tid;
            const int cc = (t & 127) * 2;                   // coefficient column (even)
            const int sb = (t < 128) ? 0 : 256;             // smem half offset

            auto ldrow = [&](int j) -> float2 {             // E[j] column pair
                return *reinterpret_cast<const float2*>(
                    A + (2 * j - mlo) * Wd + sb + cc);
            };
            auto ldodd = [&](int j) -> float2 {             // O[j] column pair
                return *reinterpret_cast<const float2*>(
                    A + (2 * j + 1 - mlo) * Wd + sb + cc);
            };

            const int b = bc >> 5;
            const int c = bc & 31;
            float* __restrict__ base = out + ((size_t)b * 128 + c) * 65536;
            float* __restrict__ sOut = base + ((t < 128) ? (size_t)0 : 64 * 65536);
            float* __restrict__ dOut = base + ((t < 128) ? 32 * 65536 : 96 * 65536);

            const int jstart = (r0 == 0)   ? 0   : (r0 - 1);
            const int jend   = (r0 == 248) ? 255 : (r0 + R);

            float2 eA = ldrow((r0 == 0) ? 1 : (r0 - 2));    // E[refl(jstart-1)]
            float2 eB = ldrow(jstart);                      // E[jstart]
            float2 Dm1 = make_float2(0.f, 0.f), Dm2 = make_float2(0.f, 0.f);

            for (int j = jstart; j <= jend; ++j) {
                const int jp = (j >= 255) ? 254 : (j + 1);
                const float2 eC = ldrow(jp);
                const float2 O  = ldodd(j);

                const float2 D = f2_fma(-0.5f, f2_add(eA, eC), O);

                if (j >= r0 && j <= r0 + R - 1) {
                    __stcs(reinterpret_cast<float2*>(dOut + (size_t)j * 256 + cc), D);
                }
                if (j >= r0 + 1) {
                    const float2 DA = (r0 == 0 && j == 1) ? D : Dm2;  // S[0] reflect
                    const float2 S = f2_fma(0.25f, f2_add(DA, D), eA);
                    __stcs(reinterpret_cast<float2*>(sOut + (size_t)(j - 1) * 256 + cc), S);
                }

                Dm2 = Dm1; Dm1 = D;
                eA = eB; eB = eC;
            }

            if (r0 == 248) {
                // S[255] = E[255] + 0.25*(2*D[254]); after final shift eA=E[255], Dm2=D[254]
                const float2 S = f2_fma(0.5f, Dm2, eA);
                __stcs(reinterpret_cast<float2*>(sOut + (size_t)255 * 256 + cc), S);
            }
        }
        __syncthreads();   // smem safe to overwrite next iteration
    }
}

extern "C" void kernel_launch(void* const* d_in, const int* in_sizes, int n_in,
                              void* d_out, int out_size) {
    const float* x = (const float*)d_in[0];
    float* out = (float*)d_out;
    (void)in_sizes; (void)n_in; (void)out_size;

    static bool attr_set = false;
    if (!attr_set) {
        cudaFuncSetAttribute(lwt53_fused_kernel,
                             cudaFuncAttributeMaxDynamicSharedMemorySize, SMEM_BYTES);
        attr_set = true;
    }

    dim3 grid(GRID);
    dim3 block(256);
    lwt53_fused_kernel<<<grid, block, SMEM_BYTES>>>(x, out);
}

// round 12
// speedup vs baseline: 1.0424x; 1.0424x over previous
#include <cuda_runtime.h>
#include <cstdint>

// Forward 5/3 lifting wavelet, 2D separable, fused half-width tile kernel.
// x: (8, 32, 512, 512) f32 -> out: (8, 128, 256, 256) f32
// out channels: [LL(0:32) | LH(32:64) | HL(64:96) | HH(96:128)]
//
//   d[i] = odd[i] - 0.5*(even[il] + even[ir]), il=(i==0)?1:i-1, ir=(i==255)?254:i+1
//   s[i] = even[i] + 0.25*(d[il] + d[ir])     (same reflected indices)
//
// Tile = 23 input rows x 256 input cols (128 coefficient cols), 128-thread
// CTAs, 23.5KB smem -> 8 CTAs/SM (32 warps): 8 independent
// load->barrier->store machines per SM for fine R/W interleave, with the same
// 188KB total smem / 40KB L1D split as the verified 4x47KB config.
// Column seam handled with predicated float4 halo loads (R6-verified formula).

static constexpr int H = 512;
static constexpr int Wd = 512;
static constexpr int R = 8;               // output rows per strip
static constexpr int NSTRIP = 256 / R;    // 32
static constexpr int NBC = 8 * 32;        // 256 images
static constexpr int TW = 256;            // tile width in input floats
static constexpr int MAXROWS = 2 * R + 7; // 23
static constexpr int SMEM_BYTES = MAXROWS * TW * 4; // 23552

static constexpr unsigned FULL = 0xffffffffu;

__device__ __forceinline__ float2 f2_add(float2 a, float2 b) {
    return make_float2(a.x + b.x, a.y + b.y);
}
__device__ __forceinline__ float2 f2_fma(float k, float2 a, float2 b) {
    return make_float2(fmaf(k, a.x, b.x), fmaf(k, a.y, b.y));
}

__global__ __launch_bounds__(128, 8)
void lwt53_fused_kernel(const float* __restrict__ x, float* __restrict__ out) {
    extern __shared__ float A[];   // [23 rows][256]; per row: s in [0,128), d in [128,256)

    const int blk    = blockIdx.x;
    const int colblk = blk & 1;            // 0: coeffs 0..127, 1: coeffs 128..255
    const int strip  = (blk >> 1) & (NSTRIP - 1);
    const int bc     = blk >> 6;
    const int r0     = strip * R;
    const int C0     = colblk << 7;        // first coefficient column of tile

    const int mlo   = max(0, 2 * r0 - 4);
    const int mhi   = min(H - 1, 2 * r0 + 2 * R + 2);
    const int nrows = mhi - mlo + 1;

    const float* __restrict__ xim =
        x + (size_t)bc * (H * Wd) + (size_t)mlo * Wd + 2 * C0;

    const int tid  = threadIdx.x;
    const int warp = tid >> 5;
    const int lane = tid & 31;

    const bool leftEdge  = (colblk == 0);
    const bool rightEdge = (colblk == 1);
    const bool haloL = (lane == 0)  && !leftEdge;
    const bool haloR = (lane == 31) && !rightEdge;

    // ================= Phase A: row lifting in registers =================
    // Warp handles whole tile rows (256 floats = 2 float4/lane). Lane l, j:
    // float4 covers coefficient pairs C0+64j+2l (eA,oA) and +1 (eB,oB).
    for (int r = warp; r < nrows; r += 4) {
        if (r == 1 && r0 > 0) continue;    // dead halo row for interior strips
        const float* __restrict__ row = xim + (size_t)r * Wd;
        float eA[2], oA[2], eB[2], oB[2];
        #pragma unroll
        for (int j = 0; j < 2; j++) {
            const float4 v = reinterpret_cast<const float4*>(row)[32 * j + lane];
            eA[j] = v.x; oA[j] = v.y; eB[j] = v.z; oB[j] = v.w;
        }
        float4 hl = make_float4(0.f, 0.f, 0.f, 0.f);
        float4 hr = make_float4(0.f, 0.f, 0.f, 0.f);
        if (haloL) hl = *reinterpret_cast<const float4*>(row - 4);   // e,o[C0-2], e,o[C0-1]
        if (haloR) hr = *reinterpret_cast<const float4*>(row + TW);  // e,o[C0+128], e,o[C0+129]

        float dA[2], dB[2];
        #pragma unroll
        for (int j = 0; j < 2; j++) {
            float up = __shfl_up_sync(FULL, eB[j], 1);
            float cp = __shfl_sync(FULL, (j > 0) ? eB[j - 1] : eB[j], 31);
            float Eprev = (lane == 0)
                ? ((j == 0) ? (leftEdge ? eB[0] : hl.z) : cp) : up;   // refl i=0 / seam
            float dn = __shfl_down_sync(FULL, eA[j], 1);
            float cn = __shfl_sync(FULL, (j < 1) ? eA[j + 1] : eA[j], 0);
            float Enext = (lane == 31)
                ? ((j == 1) ? (rightEdge ? eA[1] : hr.x) : cn) : dn;  // refl i=255 / seam
            dA[j] = oA[j] - 0.5f * (Eprev + eB[j]);
            dB[j] = oB[j] - 0.5f * (eA[j] + Enext);
        }

        // seam halo d values (meaningful only on the predicated lanes)
        const float dhl = hl.w - 0.5f * (hl.x + eA[0]);   // d[C0-1]
        const float dhr = hr.y - 0.5f * (eB[1] + hr.z);   // d[C0+128]

        float* Arow = A + r * TW;
        float2* __restrict__ srow = reinterpret_cast<float2*>(Arow);
        float2* __restrict__ drow = reinterpret_cast<float2*>(Arow + 128);
        #pragma unroll
        for (int j = 0; j < 2; j++) {
            float up = __shfl_up_sync(FULL, dB[j], 1);
            float cp = __shfl_sync(FULL, (j > 0) ? dB[j - 1] : dB[j], 31);
            float Dprev = (lane == 0)
                ? ((j == 0) ? (leftEdge ? dB[0] : dhl) : cp) : up;
            float dn = __shfl_down_sync(FULL, dA[j], 1);
            float cn = __shfl_sync(FULL, (j < 1) ? dA[j + 1] : dA[j], 0);
            float Dnext = (lane == 31)
                ? ((j == 1) ? (rightEdge ? dA[1] : dhr) : cn) : dn;
            float sA = eA[j] + 0.25f * (Dprev + dB[j]);
            float sB = eB[j] + 0.25f * (dA[j] + Dnext);
            srow[32 * j + lane] = make_float2(sA, sB);
            drow[32 * j + lane] = make_float2(dA[j], dB[j]);
        }
    }
    __syncthreads();

    // ============ Phase B: column lifting, 3-term sliding window ============
    // Thread owns a float2 column pair. t<64: s-columns (-> LL/LH);
    // t>=64: d-columns (-> HL/HH). Verified recurrence, width-256 rows.
    {
        const int t  = tid;
        const int cc = (t & 63) * 2;                    // local coefficient column (even)
        const int sb = (t < 64) ? 0 : 128;              // smem half offset

        auto ldrow = [&](int j) -> float2 {             // E[j] column pair
            return *reinterpret_cast<const float2*>(
                A + (2 * j - mlo) * TW + sb + cc);
        };
        auto ldodd = [&](int j) -> float2 {             // O[j] column pair
            return *reinterpret_cast<const float2*>(
                A + (2 * j + 1 - mlo) * TW + sb + cc);
        };

        const int b = bc >> 5;
        const int c = bc & 31;
        float* __restrict__ base = out + ((size_t)b * 128 + c) * 65536;
        float* __restrict__ sOut = base + ((t < 64) ? (size_t)0 : 64 * 65536);
        float* __restrict__ dOut = base + ((t < 64) ? 32 * 65536 : 96 * 65536);
        const int oc = C0 + cc;                         // global output column

        const int jstart = (r0 == 0)   ? 0   : (r0 - 1);
        const int jend   = (r0 == 248) ? 255 : (r0 + R);

        float2 eA = ldrow((r0 == 0) ? 1 : (r0 - 2));    // E[refl(jstart-1)]
        float2 eB = ldrow(jstart);                      // E[jstart]
        float2 Dm1 = make_float2(0.f, 0.f), Dm2 = make_float2(0.f, 0.f);

        for (int j = jstart; j <= jend; ++j) {
            const int jp = (j >= 255) ? 254 : (j + 1);
            const float2 eC = ldrow(jp);
            const float2 O  = ldodd(j);

            const float2 D = f2_fma(-0.5f, f2_add(eA, eC), O);

            if (j >= r0 && j <= r0 + R - 1) {
                __stcs(reinterpret_cast<float2*>(dOut + (size_t)j * 256 + oc), D);
            }
            if (j >= r0 + 1) {
                const float2 DA = (r0 == 0 && j == 1) ? D : Dm2;  // S[0] reflect
                const float2 S = f2_fma(0.25f, f2_add(DA, D), eA);
                __stcs(reinterpret_cast<float2*>(sOut + (size_t)(j - 1) * 256 + oc), S);
            }

            Dm2 = Dm1; Dm1 = D;
            eA = eB; eB = eC;
        }

        if (r0 == 248) {
            // S[255] = E[255] + 0.25*(2*D[254]); after final shift eA=E[255], Dm2=D[254]
            const float2 S = f2_fma(0.5f, Dm2, eA);
            __stcs(reinterpret_cast<float2*>(sOut + (size_t)255 * 256 + oc), S);
        }
    }
}

extern "C" void kernel_launch(void* const* d_in, const int* in_sizes, int n_in,
                              void* d_out, int out_size) {
    const float* x = (const float*)d_in[0];
    float* out = (float*)d_out;
    (void)in_sizes; (void)n_in; (void)out_size;

    static bool attr_set = false;
    if (!attr_set) {
        cudaFuncSetAttribute(lwt53_fused_kernel,
                             cudaFuncAttributeMaxDynamicSharedMemorySize, SMEM_BYTES);
        attr_set = true;
    }

    dim3 grid(NBC * NSTRIP * 2);   // 16384: (image, strip, colblk)
    dim3 block(128);
    lwt53_fused_kernel<<<grid, block, SMEM_BYTES>>>(x, out);
}

// round 13
// speedup vs baseline: 1.2723x; 1.2205x over previous
#include <cuda_runtime.h>
#include <cstdint>

// Forward 5/3 lifting wavelet, 2D separable, fused tile kernel.
// x: (8, 32, 512, 512) f32 -> out: (8, 128, 256, 256) f32
// out channels: [LL(0:32) | LH(32:64) | HL(64:96) | HH(96:128)]
//
//   d[i] = odd[i] - 0.5*(even[il] + even[ir]), il=(i==0)?1:i-1, ir=(i==255)?254:i+1
//   s[i] = even[i] + 0.25*(d[il] + d[ir])     (same reflected indices)
//
// R=8 rows/strip, 256-thread CTAs, 47KB smem -> 4 CTAs/SM (verified config).
// Phase A is software-pipelined: row i+1's 4 LDG.128 are issued before row i's
// shuffle/lift chain, doubling per-warp in-flight reads (the quantity DRAM%
// tracked across R9/R12).

static constexpr int H = 512;
static constexpr int Wd = 512;
static constexpr int R = 8;               // output rows per strip
static constexpr int NSTRIP = 256 / R;    // 32
static constexpr int NBC = 8 * 32;        // 256 images
static constexpr int MAXROWS = 2 * R + 7; // 23
static constexpr int SMEM_BYTES = MAXROWS * Wd * 4; // 47104

static constexpr unsigned FULL = 0xffffffffu;

__device__ __forceinline__ float2 f2_add(float2 a, float2 b) {
    return make_float2(a.x + b.x, a.y + b.y);
}
__device__ __forceinline__ float2 f2_fma(float k, float2 a, float2 b) {
    return make_float2(fmaf(k, a.x, b.x), fmaf(k, a.y, b.y));
}

__global__ __launch_bounds__(256, 4)
void lwt53_fused_kernel(const float* __restrict__ x, float* __restrict__ out) {
    extern __shared__ float A[];   // [nrows][512]; per row: s in [0,256), d in [256,512)

    const int blk   = blockIdx.x;
    const int strip = blk & (NSTRIP - 1);
    const int bc    = blk >> 5;
    const int r0    = strip * R;

    const int mlo   = max(0, 2 * r0 - 4);
    const int mhi   = min(H - 1, 2 * r0 + 2 * R + 2);
    const int nrows = mhi - mlo + 1;

    const float* __restrict__ xim = x + (size_t)bc * (H * Wd) + (size_t)mlo * Wd;

    const int tid  = threadIdx.x;
    const int warp = tid >> 5;
    const int lane = tid & 31;

    // ================= Phase A: row lifting, software-pipelined =================
    {
        // Row list for this warp (slot 1 == input row 2*r0-3 is dead for r0>0).
        int rlist[3];
        int nr = 0;
        #pragma unroll
        for (int it = 0; it < 3; ++it) {
            const int r = warp + it * 8;
            if (r < nrows && !(r == 1 && r0 > 0)) rlist[nr++] = r;
        }

        float4 cur0, cur1, cur2, cur3;
        {
            const float4* __restrict__ xr =
                reinterpret_cast<const float4*>(xim + (size_t)rlist[0] * Wd);
            cur0 = xr[lane];  cur1 = xr[32 + lane];
            cur2 = xr[64 + lane]; cur3 = xr[96 + lane];
        }

        for (int i = 0; i < nr; ++i) {
            float4 nxt0, nxt1, nxt2, nxt3;
            const bool more = (i + 1 < nr);
            if (more) {
                const float4* __restrict__ xr =
                    reinterpret_cast<const float4*>(xim + (size_t)rlist[i + 1] * Wd);
                nxt0 = xr[lane];  nxt1 = xr[32 + lane];
                nxt2 = xr[64 + lane]; nxt3 = xr[96 + lane];
            }

            float eA[4] = {cur0.x, cur1.x, cur2.x, cur3.x};
            float oA[4] = {cur0.y, cur1.y, cur2.y, cur3.y};
            float eB[4] = {cur0.z, cur1.z, cur2.z, cur3.z};
            float oB[4] = {cur0.w, cur1.w, cur2.w, cur3.w};

            float dA[4], dB[4];
            #pragma unroll
            for (int j = 0; j < 4; j++) {
                float up = __shfl_up_sync(FULL, eB[j], 1);
                float cp = __shfl_sync(FULL, (j > 0) ? eB[j - 1] : eB[j], 31);
                float Eprev = (lane == 0) ? ((j == 0) ? eB[0] : cp) : up;   // refl i=0
                float dn = __shfl_down_sync(FULL, eA[j], 1);
                float cn = __shfl_sync(FULL, (j < 3) ? eA[j + 1] : eA[j], 0);
                float Enext = (lane == 31) ? ((j == 3) ? eA[3] : cn) : dn;  // refl i=255
                dA[j] = oA[j] - 0.5f * (Eprev + eB[j]);
                dB[j] = oB[j] - 0.5f * (eA[j] + Enext);
            }

            float* Arow = A + rlist[i] * Wd;
            float2* __restrict__ srow = reinterpret_cast<float2*>(Arow);
            float2* __restrict__ drow = reinterpret_cast<float2*>(Arow + 256);
            #pragma unroll
            for (int j = 0; j < 4; j++) {
                float up = __shfl_up_sync(FULL, dB[j], 1);
                float cp = __shfl_sync(FULL, (j > 0) ? dB[j - 1] : dB[j], 31);
                float Dprev = (lane == 0) ? ((j == 0) ? dB[0] : cp) : up;
                float dn = __shfl_down_sync(FULL, dA[j], 1);
                float cn = __shfl_sync(FULL, (j < 3) ? dA[j + 1] : dA[j], 0);
                float Dnext = (lane == 31) ? ((j == 3) ? dA[3] : cn) : dn;
                float sA = eA[j] + 0.25f * (Dprev + dB[j]);
                float sB = eB[j] + 0.25f * (dA[j] + Dnext);
                srow[32 * j + lane] = make_float2(sA, sB);
                drow[32 * j + lane] = make_float2(dA[j], dB[j]);
            }

            if (more) {
                cur0 = nxt0; cur1 = nxt1; cur2 = nxt2; cur3 = nxt3;
            }
        }
    }
    __syncthreads();

    // ============ Phase B: column lifting, 3-term sliding window ============
    // Thread owns a float2 column pair. t<128: s-columns (-> LL/LH);
    // t>=128: d-columns (-> HL/HH).
    {
        const int t  = tid;
        const int cc = (t & 127) * 2;                   // coefficient column (even)
        const int sb = (t < 128) ? 0 : 256;             // smem half offset

        auto ldrow = [&](int j) -> float2 {             // E[j] column pair
            return *reinterpret_cast<const float2*>(
                A + (2 * j - mlo) * Wd + sb + cc);
        };
        auto ldodd = [&](int j) -> float2 {             // O[j] column pair
            return *reinterpret_cast<const float2*>(
                A + (2 * j + 1 - mlo) * Wd + sb + cc);
        };

        const int b = bc >> 5;
        const int c = bc & 31;
        float* __restrict__ base = out + ((size_t)b * 128 + c) * 65536;
        float* __restrict__ sOut = base + ((t < 128) ? (size_t)0 : 64 * 65536);
        float* __restrict__ dOut = base + ((t < 128) ? 32 * 65536 : 96 * 65536);

        const int jstart = (r0 == 0)   ? 0   : (r0 - 1);
        const int jend   = (r0 == 248) ? 255 : (r0 + R);

        float2 eA = ldrow((r0 == 0) ? 1 : (r0 - 2));    // E[refl(jstart-1)]
        float2 eB = ldrow(jstart);                      // E[jstart]
        float2 Dm1 = make_float2(0.f, 0.f), Dm2 = make_float2(0.f, 0.f);

        for (int j = jstart; j <= jend; ++j) {
            const int jp = (j >= 255) ? 254 : (j + 1);
            const float2 eC = ldrow(jp);
            const float2 O  = ldodd(j);

            const float2 D = f2_fma(-0.5f, f2_add(eA, eC), O);

            if (j >= r0 && j <= r0 + R - 1) {
                __stcs(reinterpret_cast<float2*>(dOut + (size_t)j * 256 + cc), D);
            }
            if (j >= r0 + 1) {
                const float2 DA = (r0 == 0 && j == 1) ? D : Dm2;  // S[0] reflect
                const float2 S = f2_fma(0.25f, f2_add(DA, D), eA);
                __stcs(reinterpret_cast<float2*>(sOut + (size_t)(j - 1) * 256 + cc), S);
            }

            Dm2 = Dm1; Dm1 = D;
            eA = eB; eB = eC;
        }

        if (r0 == 248) {
            // S[255] = E[255] + 0.25*(2*D[254]); after final shift eA=E[255], Dm2=D[254]
            const float2 S = f2_fma(0.5f, Dm2, eA);
            __stcs(reinterpret_cast<float2*>(sOut + (size_t)255 * 256 + cc), S);
        }
    }
}

extern "C" void kernel_launch(void* const* d_in, const int* in_sizes, int n_in,
                              void* d_out, int out_size) {
    const float* x = (const float*)d_in[0];
    float* out = (float*)d_out;
    (void)in_sizes; (void)n_in; (void)out_size;

    static bool attr_set = false;
    if (!attr_set) {
        cudaFuncSetAttribute(lwt53_fused_kernel,
                             cudaFuncAttributeMaxDynamicSharedMemorySize, SMEM_BYTES);
        attr_set = true;
    }

    dim3 grid(NBC * NSTRIP);   // 8192
    dim3 block(256);
    lwt53_fused_kernel<<<grid, block, SMEM_BYTES>>>(x, out);
}

// round 14
// speedup vs baseline: 1.2786x; 1.0050x over previous
#include <cuda_runtime.h>
#include <cstdint>

// Forward 5/3 lifting wavelet, 2D separable, fused tile kernel.
// x: (8, 32, 512, 512) f32 -> out: (8, 128, 256, 256) f32
// out channels: [LL(0:32) | LH(32:64) | HL(64:96) | HH(96:128)]
//
//   d[i] = odd[i] - 0.5*(even[il] + even[ir]), il=(i==0)?1:i-1, ir=(i==255)?254:i+1
//   s[i] = even[i] + 0.25*(d[il] + d[ir])     (same reflected indices)
//
// R=8 rows/strip, 256-thread CTAs, 47KB smem -> 4 CTAs/SM. Phase A:
// software-pipelined LDG (R13 win) + rotation shuffles: the (shfl_up +
// lane31-broadcast) pair per j collapses into one variable-lane shuffle with
// seam value pre-selected on the source lane -> 16 shuffles/row instead of 32.

static constexpr int H = 512;
static constexpr int Wd = 512;
static constexpr int R = 8;               // output rows per strip
static constexpr int NSTRIP = 256 / R;    // 32
static constexpr int NBC = 8 * 32;        // 256 images
static constexpr int MAXROWS = 2 * R + 7; // 23
static constexpr int SMEM_BYTES = MAXROWS * Wd * 4; // 47104

static constexpr unsigned FULL = 0xffffffffu;

__device__ __forceinline__ float2 f2_add(float2 a, float2 b) {
    return make_float2(a.x + b.x, a.y + b.y);
}
__device__ __forceinline__ float2 f2_fma(float k, float2 a, float2 b) {
    return make_float2(fmaf(k, a.x, b.x), fmaf(k, a.y, b.y));
}

__global__ __launch_bounds__(256, 4)
void lwt53_fused_kernel(const float* __restrict__ x, float* __restrict__ out) {
    extern __shared__ float A[];   // [nrows][512]; per row: s in [0,256), d in [256,512)

    const int blk   = blockIdx.x;
    const int strip = blk & (NSTRIP - 1);
    const int bc    = blk >> 5;
    const int r0    = strip * R;

    const int mlo   = max(0, 2 * r0 - 4);
    const int mhi   = min(H - 1, 2 * r0 + 2 * R + 2);
    const int nrows = mhi - mlo + 1;

    const float* __restrict__ xim = x + (size_t)bc * (H * Wd) + (size_t)mlo * Wd;

    const int tid  = threadIdx.x;
    const int warp = tid >> 5;
    const int lane = tid & 31;
    const int lnm1 = (lane + 31) & 31;     // rotate-up source lane
    const int lnp1 = (lane + 1) & 31;      // rotate-down source lane

    // ================= Phase A: row lifting, pipelined + rotation shuffles ====
    {
        int rlist[3];
        int nr = 0;
        #pragma unroll
        for (int it = 0; it < 3; ++it) {
            const int r = warp + it * 8;
            if (r < nrows && !(r == 1 && r0 > 0)) rlist[nr++] = r;
        }

        float4 cur0, cur1, cur2, cur3;
        {
            const float4* __restrict__ xr =
                reinterpret_cast<const float4*>(xim + (size_t)rlist[0] * Wd);
            cur0 = xr[lane];  cur1 = xr[32 + lane];
            cur2 = xr[64 + lane]; cur3 = xr[96 + lane];
        }

        for (int i = 0; i < nr; ++i) {
            float4 nxt0, nxt1, nxt2, nxt3;
            const bool more = (i + 1 < nr);
            if (more) {
                const float4* __restrict__ xr =
                    reinterpret_cast<const float4*>(xim + (size_t)rlist[i + 1] * Wd);
                nxt0 = xr[lane];  nxt1 = xr[32 + lane];
                nxt2 = xr[64 + lane]; nxt3 = xr[96 + lane];
            }

            float eA[4] = {cur0.x, cur1.x, cur2.x, cur3.x};
            float oA[4] = {cur0.y, cur1.y, cur2.y, cur3.y};
            float eB[4] = {cur0.z, cur1.z, cur2.z, cur3.z};
            float oB[4] = {cur0.w, cur1.w, cur2.w, cur3.w};

            // d[i0]   = oA - 0.5*(Eprev + eB)   (Eprev = e[i0-1])
            // d[i0+1] = oB - 0.5*(eA + Enext)   (Enext = e[i0+2])
            float dA[4], dB[4];
            #pragma unroll
            for (int j = 0; j < 4; j++) {
                const float srcP = (j > 0 && lane == 31) ? eB[j - 1] : eB[j];
                float Eprev = __shfl_sync(FULL, srcP, lnm1);
                if (j == 0) Eprev = (lane == 0) ? eB[0] : Eprev;      // refl i=0
                const float srcN = (j < 3 && lane == 0) ? eA[j + 1] : eA[j];
                float Enext = __shfl_sync(FULL, srcN, lnp1);
                if (j == 3) Enext = (lane == 31) ? eA[3] : Enext;     // refl i=255
                dA[j] = oA[j] - 0.5f * (Eprev + eB[j]);
                dB[j] = oB[j] - 0.5f * (eA[j] + Enext);
            }

            // s[i0]   = eA + 0.25*(Dprev + dB)  (Dprev = d[i0-1])
            // s[i0+1] = eB + 0.25*(dA + Dnext)  (Dnext = d[i0+2])
            float* Arow = A + rlist[i] * Wd;
            float2* __restrict__ srow = reinterpret_cast<float2*>(Arow);
            float2* __restrict__ drow = reinterpret_cast<float2*>(Arow + 256);
            #pragma unroll
            for (int j = 0; j < 4; j++) {
                const float srcP = (j > 0 && lane == 31) ? dB[j - 1] : dB[j];
                float Dprev = __shfl_sync(FULL, srcP, lnm1);
                if (j == 0) Dprev = (lane == 0) ? dB[0] : Dprev;      // refl i=0
                const float srcN = (j < 3 && lane == 0) ? dA[j + 1] : dA[j];
                float Dnext = __shfl_sync(FULL, srcN, lnp1);
                if (j == 3) Dnext = (lane == 31) ? dA[3] : Dnext;     // refl i=255
                const float sA = eA[j] + 0.25f * (Dprev + dB[j]);
                const float sB = eB[j] + 0.25f * (dA[j] + Dnext);
                srow[32 * j + lane] = make_float2(sA, sB);
                drow[32 * j + lane] = make_float2(dA[j], dB[j]);
            }

            if (more) {
                cur0 = nxt0; cur1 = nxt1; cur2 = nxt2; cur3 = nxt3;
            }
        }
    }
    __syncthreads();

    // ============ Phase B: column lifting, 3-term sliding window ============
    // Thread owns a float2 column pair. t<128: s-columns (-> LL/LH);
    // t>=128: d-columns (-> HL/HH).
    {
        const int t  = tid;
        const int cc = (t & 127) * 2;                   // coefficient column (even)
        const int sb = (t < 128) ? 0 : 256;             // smem half offset

        auto ldrow = [&](int j) -> float2 {             // E[j] column pair
            return *reinterpret_cast<const float2*>(
                A + (2 * j - mlo) * Wd + sb + cc);
        };
        auto ldodd = [&](int j) -> float2 {             // O[j] column pair
            return *reinterpret_cast<const float2*>(
                A + (2 * j + 1 - mlo) * Wd + sb + cc);
        };

        const int b = bc >> 5;
        const int c = bc & 31;
        float* __restrict__ base = out + ((size_t)b * 128 + c) * 65536;
        float* __restrict__ sOut = base + ((t < 128) ? (size_t)0 : 64 * 65536);
        float* __restrict__ dOut = base + ((t < 128) ? 32 * 65536 : 96 * 65536);

        const int jstart = (r0 == 0)   ? 0   : (r0 - 1);
        const int jend   = (r0 == 248) ? 255 : (r0 + R);

        float2 eA = ldrow((r0 == 0) ? 1 : (r0 - 2));    // E[refl(jstart-1)]
        float2 eB = ldrow(jstart);                      // E[jstart]
        float2 Dm1 = make_float2(0.f, 0.f), Dm2 = make_float2(0.f, 0.f);

        for (int j = jstart; j <= jend; ++j) {
            const int jp = (j >= 255) ? 254 : (j + 1);
            const float2 eC = ldrow(jp);
            const float2 O  = ldodd(j);

            const float2 D = f2_fma(-0.5f, f2_add(eA, eC), O);

            if (j >= r0 && j <= r0 + R - 1) {
                __stcs(reinterpret_cast<float2*>(dOut + (size_t)j * 256 + cc), D);
            }
            if (j >= r0 + 1) {
                const float2 DA = (r0 == 0 && j == 1) ? D : Dm2;  // S[0] reflect
                const float2 S = f2_fma(0.25f, f2_add(DA, D), eA);
                __stcs(reinterpret_cast<float2*>(sOut + (size_t)(j - 1) * 256 + cc), S);
            }

            Dm2 = Dm1; Dm1 = D;
            eA = eB; eB = eC;
        }

        if (r0 == 248) {
            // S[255] = E[255] + 0.25*(2*D[254]); after final shift eA=E[255], Dm2=D[254]
            const float2 S = f2_fma(0.5f, Dm2, eA);
            __stcs(reinterpret_cast<float2*>(sOut + (size_t)255 * 256 + cc), S);
        }
    }
}

extern "C" void kernel_launch(void* const* d_in, const int* in_sizes, int n_in,
                              void* d_out, int out_size) {
    const float* x = (const float*)d_in[0];
    float* out = (float*)d_out;
    (void)in_sizes; (void)n_in; (void)out_size;

    static bool attr_set = false;
    if (!attr_set) {
        cudaFuncSetAttribute(lwt53_fused_kernel,
                             cudaFuncAttributeMaxDynamicSharedMemorySize, SMEM_BYTES);
        attr_set = true;
    }

    dim3 grid(NBC * NSTRIP);   // 8192
    dim3 block(256);
    lwt53_fused_kernel<<<grid, block, SMEM_BYTES>>>(x, out);
}

// round 15
// speedup vs baseline: 1.2806x; 1.0015x over previous
#include <cuda_runtime.h>
#include <cstdint>

// Forward 5/3 lifting wavelet, 2D separable, fused tile kernel.
// x: (8, 32, 512, 512) f32 -> out: (8, 128, 256, 256) f32
// out channels: [LL(0:32) | LH(32:64) | HL(64:96) | HH(96:128)]
//
//   d[i] = odd[i] - 0.5*(even[il] + even[ir]), il=(i==0)?1:i-1, ir=(i==255)?254:i+1
//   s[i] = even[i] + 0.25*(d[il] + d[ir])     (same reflected indices)
//
// R=8 rows/strip, 256-thread CTAs, 47KB smem -> 4 CTAs/SM. Phase A:
// software-pipelined LDG + rotation shuffles (R13/R14 wins). Phase B:
// interior strips (30 of 32) take a fully-unrolled 10-iteration path with
// compile-time predicates so the compiler can batch LDS and drop branches.

static constexpr int H = 512;
static constexpr int Wd = 512;
static constexpr int R = 8;               // output rows per strip
static constexpr int NSTRIP = 256 / R;    // 32
static constexpr int NBC = 8 * 32;        // 256 images
static constexpr int MAXROWS = 2 * R + 7; // 23
static constexpr int SMEM_BYTES = MAXROWS * Wd * 4; // 47104

static constexpr unsigned FULL = 0xffffffffu;

__device__ __forceinline__ float2 f2_add(float2 a, float2 b) {
    return make_float2(a.x + b.x, a.y + b.y);
}
__device__ __forceinline__ float2 f2_fma(float k, float2 a, float2 b) {
    return make_float2(fmaf(k, a.x, b.x), fmaf(k, a.y, b.y));
}

__global__ __launch_bounds__(256, 4)
void lwt53_fused_kernel(const float* __restrict__ x, float* __restrict__ out) {
    extern __shared__ float A[];   // [nrows][512]; per row: s in [0,256), d in [256,512)

    const int blk   = blockIdx.x;
    const int strip = blk & (NSTRIP - 1);
    const int bc    = blk >> 5;
    const int r0    = strip * R;

    const int mlo   = max(0, 2 * r0 - 4);
    const int mhi   = min(H - 1, 2 * r0 + 2 * R + 2);
    const int nrows = mhi - mlo + 1;

    const float* __restrict__ xim = x + (size_t)bc * (H * Wd) + (size_t)mlo * Wd;

    const int tid  = threadIdx.x;
    const int warp = tid >> 5;
    const int lane = tid & 31;
    const int lnm1 = (lane + 31) & 31;     // rotate-up source lane
    const int lnp1 = (lane + 1) & 31;      // rotate-down source lane

    // ================= Phase A: row lifting, pipelined + rotation shuffles ====
    {
        int rlist[3];
        int nr = 0;
        #pragma unroll
        for (int it = 0; it < 3; ++it) {
            const int r = warp + it * 8;
            if (r < nrows && !(r == 1 && r0 > 0)) rlist[nr++] = r;
        }

        float4 cur0, cur1, cur2, cur3;
        {
            const float4* __restrict__ xr =
                reinterpret_cast<const float4*>(xim + (size_t)rlist[0] * Wd);
            cur0 = xr[lane];  cur1 = xr[32 + lane];
            cur2 = xr[64 + lane]; cur3 = xr[96 + lane];
        }

        for (int i = 0; i < nr; ++i) {
            float4 nxt0, nxt1, nxt2, nxt3;
            const bool more = (i + 1 < nr);
            if (more) {
                const float4* __restrict__ xr =
                    reinterpret_cast<const float4*>(xim + (size_t)rlist[i + 1] * Wd);
                nxt0 = xr[lane];  nxt1 = xr[32 + lane];
                nxt2 = xr[64 + lane]; nxt3 = xr[96 + lane];
            }

            float eA[4] = {cur0.x, cur1.x, cur2.x, cur3.x};
            float oA[4] = {cur0.y, cur1.y, cur2.y, cur3.y};
            float eB[4] = {cur0.z, cur1.z, cur2.z, cur3.z};
            float oB[4] = {cur0.w, cur1.w, cur2.w, cur3.w};

            float dA[4], dB[4];
            #pragma unroll
            for (int j = 0; j < 4; j++) {
                const float srcP = (j > 0 && lane == 31) ? eB[j - 1] : eB[j];
                float Eprev = __shfl_sync(FULL, srcP, lnm1);
                if (j == 0) Eprev = (lane == 0) ? eB[0] : Eprev;      // refl i=0
                const float srcN = (j < 3 && lane == 0) ? eA[j + 1] : eA[j];
                float Enext = __shfl_sync(FULL, srcN, lnp1);
                if (j == 3) Enext = (lane == 31) ? eA[3] : Enext;     // refl i=255
                dA[j] = oA[j] - 0.5f * (Eprev + eB[j]);
                dB[j] = oB[j] - 0.5f * (eA[j] + Enext);
            }

            float* Arow = A + rlist[i] * Wd;
            float2* __restrict__ srow = reinterpret_cast<float2*>(Arow);
            float2* __restrict__ drow = reinterpret_cast<float2*>(Arow + 256);
            #pragma unroll
            for (int j = 0; j < 4; j++) {
                const float srcP = (j > 0 && lane == 31) ? dB[j - 1] : dB[j];
                float Dprev = __shfl_sync(FULL, srcP, lnm1);
                if (j == 0) Dprev = (lane == 0) ? dB[0] : Dprev;      // refl i=0
                const float srcN = (j < 3 && lane == 0) ? dA[j + 1] : dA[j];
                float Dnext = __shfl_sync(FULL, srcN, lnp1);
                if (j == 3) Dnext = (lane == 31) ? dA[3] : Dnext;     // refl i=255
                const float sA = eA[j] + 0.25f * (Dprev + dB[j]);
                const float sB = eB[j] + 0.25f * (dA[j] + Dnext);
                srow[32 * j + lane] = make_float2(sA, sB);
                drow[32 * j + lane] = make_float2(dA[j], dB[j]);
            }

            if (more) {
                cur0 = nxt0; cur1 = nxt1; cur2 = nxt2; cur3 = nxt3;
            }
        }
    }
    __syncthreads();

    // ============ Phase B: column lifting, 3-term sliding window ============
    // Thread owns a float2 column pair. t<128: s-columns (-> LL/LH);
    // t>=128: d-columns (-> HL/HH). Interior strips take a fully unrolled
    // 10-iteration path (all predicates compile-time).
    {
        const int t  = tid;
        const int cc = (t & 127) * 2;                   // coefficient column (even)
        const int sb = (t < 128) ? 0 : 256;             // smem half offset

        auto ldrow = [&](int j) -> float2 {             // E[j] column pair
            return *reinterpret_cast<const float2*>(
                A + (2 * j - mlo) * Wd + sb + cc);
        };
        auto ldodd = [&](int j) -> float2 {             // O[j] column pair
            return *reinterpret_cast<const float2*>(
                A + (2 * j + 1 - mlo) * Wd + sb + cc);
        };

        const int b = bc >> 5;
        const int c = bc & 31;
        float* __restrict__ base = out + ((size_t)b * 128 + c) * 65536;
        float* __restrict__ sOut = base + ((t < 128) ? (size_t)0 : 64 * 65536);
        float* __restrict__ dOut = base + ((t < 128) ? 32 * 65536 : 96 * 65536);

        if (r0 != 0 && r0 != 248) {
            // -------- interior strip: 10 iterations, fully unrolled --------
            // j = r0-1+q, q=0..9 ; no reflections possible.
            float2 eA = ldrow(r0 - 2);
            float2 eB = ldrow(r0 - 1);
            float2 Dm1 = make_float2(0.f, 0.f), Dm2 = make_float2(0.f, 0.f);

            #pragma unroll
            for (int q = 0; q < 10; ++q) {
                const int j = r0 - 1 + q;
                const float2 eC = ldrow(j + 1);
                const float2 O  = ldodd(j);

                const float2 D = f2_fma(-0.5f, f2_add(eA, eC), O);

                if (q >= 1 && q <= 8) {   // j in [r0, r0+7]
                    __stcs(reinterpret_cast<float2*>(dOut + (size_t)j * 256 + cc), D);
                }
                if (q >= 2) {             // S[j-1], j-1 in [r0, r0+7]
                    const float2 S = f2_fma(0.25f, f2_add(Dm2, D), eA);
                    __stcs(reinterpret_cast<float2*>(sOut + (size_t)(j - 1) * 256 + cc), S);
                }

                Dm2 = Dm1; Dm1 = D;
                eA = eB; eB = eC;
            }
        } else {
            // -------- edge strips: generic (verified) path --------
            const int jstart = (r0 == 0)   ? 0   : (r0 - 1);
            const int jend   = (r0 == 248) ? 255 : (r0 + R);

            float2 eA = ldrow((r0 == 0) ? 1 : (r0 - 2));
            float2 eB = ldrow(jstart);
            float2 Dm1 = make_float2(0.f, 0.f), Dm2 = make_float2(0.f, 0.f);

            for (int j = jstart; j <= jend; ++j) {
                const int jp = (j >= 255) ? 254 : (j + 1);
                const float2 eC = ldrow(jp);
                const float2 O  = ldodd(j);

                const float2 D = f2_fma(-0.5f, f2_add(eA, eC), O);

                if (j >= r0 && j <= r0 + R - 1) {
                    __stcs(reinterpret_cast<float2*>(dOut + (size_t)j * 256 + cc), D);
                }
                if (j >= r0 + 1) {
                    const float2 DA = (r0 == 0 && j == 1) ? D : Dm2;  // S[0] reflect
                    const float2 S = f2_fma(0.25f, f2_add(DA, D), eA);
                    __stcs(reinterpret_cast<float2*>(sOut + (size_t)(j - 1) * 256 + cc), S);
                }

                Dm2 = Dm1; Dm1 = D;
                eA = eB; eB = eC;
            }

            if (r0 == 248) {
                // S[255] = E[255] + 0.25*(2*D[254]); after final shift eA=E[255], Dm2=D[254]
                const float2 S = f2_fma(0.5f, Dm2, eA);
                __stcs(reinterpret_cast<float2*>(sOut + (size_t)255 * 256 + cc), S);
            }
        }
    }
}

extern "C" void kernel_launch(void* const* d_in, const int* in_sizes, int n_in,
                              void* d_out, int out_size) {
    const float* x = (const float*)d_in[0];
    float* out = (float*)d_out;
    (void)in_sizes; (void)n_in; (void)out_size;

    static bool attr_set = false;
    if (!attr_set) {
        cudaFuncSetAttribute(lwt53_fused_kernel,
                             cudaFuncAttributeMaxDynamicSharedMemorySize, SMEM_BYTES);
        attr_set = true;
    }

    dim3 grid(NBC * NSTRIP);   // 8192
    dim3 block(256);
    lwt53_fused_kernel<<<grid, block, SMEM_BYTES>>>(x, out);
}